// round 6
// baseline (speedup 1.0000x reference)
#include <cuda_runtime.h>

// GRU persistent kernel v2.
// - 128 CTAs x 256 threads, warp tile 16 rows x 4 cols (thread: 2 rows x 1 col)
//   -> per-warp weight SMEM traffic cut 4x vs v1, inputs conflict-free.
// - h/rh/x SMEM rows padded to stride == 4 (mod 32) floats: conflict-free
//   LDS.128 subphases for the 8-lane row reads.
// - Barriers are per-batch-tile GROUPS of 16 CTAs (batch tiles independent).
// - Overlap: barrier A hides candidate x-part; barrier B hides x(t+1) prefetch
//   plus the z/r x-part for t+1 (h-independent).

#define SEQLEN 512
#define BATCHN 256
#define INPUTN 128
#define HID    256
#define NBLK   128
#define NBT    8       // batch-tile groups
#define BT     32      // rows per batch tile
#define HS     16      // hidden cols per slice
#define NGRP   16      // CTAs per barrier group
#define WPAD   388     // weight row pad (floats), 97 x 16B
#define WP4    97
#define GS4    (HS*WP4)    // 1552 16B-chunks per gate
#define HPAD   260        // h/rh row pad: 260 % 32 == 4 -> conflict-free
#define H16    65         // 260/4 16B chunks
#define XPAD   132        // x row pad
#define X16    33

__device__ float    g_h [BATCHN * HID];
__device__ float    g_rh[BATCHN * HID];
__device__ unsigned g_count[NBT * 32];   // padded: one flag per 128B
__device__ unsigned g_sense[NBT * 32];

__device__ __forceinline__ void ffma2(unsigned long long &acc,
                                      unsigned long long a,
                                      unsigned long long b) {
    asm("fma.rn.f32x2 %0, %1, %2, %0;" : "+l"(acc) : "l"(a), "l"(b));
}
__device__ __forceinline__ float f2sum(unsigned long long v) {
    return __uint_as_float((unsigned)v) + __uint_as_float((unsigned)(v >> 32));
}
__device__ __forceinline__ float sigmoidf_(float a) {
    return 1.0f / (1.0f + __expf(-a));
}
__device__ __forceinline__ float tanhf_(float a) {
    return 2.0f / (1.0f + __expf(-2.0f * a)) - 1.0f;
}

// group barrier: arrive (non-blocking) ... overlap work ... wait
__device__ __forceinline__ void grp_arrive(unsigned &sense, unsigned *cnt, unsigned *sns) {
    __syncthreads();
    if (threadIdx.x == 0) {
        sense ^= 1u;
        __threadfence();
        unsigned prev = atomicAdd(cnt, 1u);
        if (prev == NGRP - 1u) {
            atomicExch(cnt, 0u);
            __threadfence();
            atomicExch(sns, sense);
        }
    }
}
__device__ __forceinline__ void grp_wait(unsigned sense, unsigned *sns) {
    if (threadIdx.x == 0) {
        while (*((volatile unsigned *)sns) != sense) { }
        __threadfence();
    }
    __syncthreads();
}

__global__ void __launch_bounds__(256, 1)
gru_persistent(const float* __restrict__ X,
               const float* __restrict__ Wz, const float* __restrict__ bz,
               const float* __restrict__ Wr, const float* __restrict__ br,
               const float* __restrict__ Wc, const float* __restrict__ bc,
               float* __restrict__ out)
{
    extern __shared__ float sm[];
    float* sW   = sm;                          // 3*16*388 = 18624 floats
    float* sB   = sm + 3 * HS * WPAD;          // 48 floats
    float* h_s  = sB + 48;                     // 32 x 260
    float* rh_s = h_s + BT * HPAD;             // 32 x 260
    float* x_s  = rh_s + BT * HPAD;            // 32 x 132

    const int tid   = threadIdx.x;
    const int bt    = blockIdx.x & (NBT - 1);
    const int hsb   = blockIdx.x >> 3;
    const int bbase = bt * BT;
    const int jbase = hsb * HS;

    unsigned *cnt = &g_count[bt * 32];
    unsigned *sns = &g_sense[bt * 32];

    unsigned sense = 0;
    if (tid == 0) sense = *((volatile unsigned *)sns);

    // ---- weights into SMEM (row-major per col, padded) ----
    {
        float4* sW4 = (float4*)sW;
        #pragma unroll
        for (int g = 0; g < 3; g++) {
            const float* W = (g == 0) ? Wz : (g == 1) ? Wr : Wc;
            const float4* W4 = (const float4*)W;
            for (int idx = tid; idx < HS * 96; idx += 256) {
                int j = idx / 96, k4 = idx % 96;
                sW4[g * GS4 + j * WP4 + k4] = W4[(jbase + j) * 96 + k4];
            }
        }
        if (tid < HS) {
            sB[tid]          = bz[jbase + tid];
            sB[HS + tid]     = br[jbase + tid];
            sB[2 * HS + tid] = bc[jbase + tid];
        }
        for (int i = tid; i < BT * HPAD; i += 256) h_s[i] = 0.0f;   // h0 = 0
    }
    // x tile for t=0
    for (int idx = tid; idx < BT * 32; idx += 256) {
        int row = idx >> 5, c4 = idx & 31;
        *(float4*)(x_s + row * XPAD + c4 * 4) =
            ((const float4*)X)[(size_t)(bbase + row) * (SEQLEN * INPUTN / 4) + c4];
    }
    __syncthreads();

    // lane map: warp tile 16 rows x 4 cols, thread 2 rows x 1 col
    const int w    = tid >> 5;
    const int l    = tid & 31;
    const int txi  = l >> 3;                 // 0..3  (col within warp)
    const int ty   = l & 7;                  // 0..7  (row within subphase)
    const int cg   = w & 3;                  // warp col group
    const int rg   = w >> 2;                 // warp row group (0,1)
    const int jloc = cg * 4 + txi;           // 0..15
    const int jg   = jbase + jloc;           // global hidden col
    const int row0 = rg * 16 + ty;
    const int row1 = row0 + 8;

    const ulonglong2* wz2 = (const ulonglong2*)sW + jloc * WP4;
    const ulonglong2* wr2 = wz2 + GS4;
    const ulonglong2* wc2 = wz2 + 2 * GS4;
    const ulonglong2* h0p  = (const ulonglong2*)h_s  + row0 * H16;
    const ulonglong2* h1p  = (const ulonglong2*)h_s  + row1 * H16;
    const ulonglong2* rh0p = (const ulonglong2*)rh_s + row0 * H16;
    const ulonglong2* rh1p = (const ulonglong2*)rh_s + row1 * H16;
    const ulonglong2* x0p  = (const ulonglong2*)x_s  + row0 * X16;
    const ulonglong2* x1p  = (const ulonglong2*)x_s  + row1 * X16;

    const float bzr = sB[jloc];
    const float brr = sB[HS + jloc];
    const float bcr = sB[2 * HS + jloc];

    // z/r x-part for t=0 (h-independent)
    unsigned long long az0 = 0, az1 = 0, ar0 = 0, ar1 = 0;
    #pragma unroll 8
    for (int k = 0; k < 32; k++) {
        ulonglong2 xv0 = x0p[k], xv1 = x1p[k];
        ulonglong2 wzv = wz2[64 + k], wrv = wr2[64 + k];
        ffma2(az0, wzv.x, xv0.x); ffma2(az0, wzv.y, xv0.y);
        ffma2(ar0, wrv.x, xv0.x); ffma2(ar0, wrv.y, xv0.y);
        ffma2(az1, wzv.x, xv1.x); ffma2(az1, wzv.y, xv1.y);
        ffma2(ar1, wrv.x, xv1.x); ffma2(ar1, wrv.y, xv1.y);
    }

    for (int t = 0; t < SEQLEN; t++) {
        // ---------- phase 1: z, r (h-part; x-part already accumulated) ----------
        #pragma unroll 8
        for (int k = 0; k < 64; k++) {
            ulonglong2 hv0 = h0p[k], hv1 = h1p[k];
            ulonglong2 wzv = wz2[k], wrv = wr2[k];
            ffma2(az0, wzv.x, hv0.x); ffma2(az0, wzv.y, hv0.y);
            ffma2(ar0, wrv.x, hv0.x); ffma2(ar0, wrv.y, hv0.y);
            ffma2(az1, wzv.x, hv1.x); ffma2(az1, wzv.y, hv1.y);
            ffma2(ar1, wrv.x, hv1.x); ffma2(ar1, wrv.y, hv1.y);
        }
        float z0 = sigmoidf_(f2sum(az0) + bzr);
        float z1 = sigmoidf_(f2sum(az1) + bzr);
        float r0 = sigmoidf_(f2sum(ar0) + brr);
        float r1 = sigmoidf_(f2sum(ar1) + brr);
        float h0old = h_s[row0 * HPAD + jg];
        float h1old = h_s[row1 * HPAD + jg];
        g_rh[(bbase + row0) * HID + jg] = r0 * h0old;
        g_rh[(bbase + row1) * HID + jg] = r1 * h1old;

        grp_arrive(sense, cnt, sns);                 // barrier A arrive

        // overlap A: candidate x-part (independent of rh)
        unsigned long long ac0 = 0, ac1 = 0;
        #pragma unroll 8
        for (int k = 0; k < 32; k++) {
            ulonglong2 xv0 = x0p[k], xv1 = x1p[k];
            ulonglong2 wcv = wc2[64 + k];
            ffma2(ac0, wcv.x, xv0.x); ffma2(ac0, wcv.y, xv0.y);
            ffma2(ac1, wcv.x, xv1.x); ffma2(ac1, wcv.y, xv1.y);
        }

        grp_wait(sense, sns);                        // barrier A wait

        // gather full r*h rows for our batch tile
        for (int idx = tid; idx < BT * 64; idx += 256) {
            int row = idx >> 6, c4 = idx & 63;
            *(float4*)(rh_s + row * HPAD + c4 * 4) =
                ((const float4*)g_rh)[(bbase + row) * 64 + c4];
        }
        __syncthreads();

        // ---------- phase 2: candidate h-part + update ----------
        #pragma unroll 8
        for (int k = 0; k < 64; k++) {
            ulonglong2 rv0 = rh0p[k], rv1 = rh1p[k];
            ulonglong2 wcv = wc2[k];
            ffma2(ac0, wcv.x, rv0.x); ffma2(ac0, wcv.y, rv0.y);
            ffma2(ac1, wcv.x, rv1.x); ffma2(ac1, wcv.y, rv1.y);
        }
        float c0 = tanhf_(f2sum(ac0) + bcr);
        float c1 = tanhf_(f2sum(ac1) + bcr);
        float hn0 = h0old + z0 * (c0 - h0old);       // (1-z)h + z*c
        float hn1 = h1old + z1 * (c1 - h1old);
        g_h[(bbase + row0) * HID + jg] = hn0;
        g_h[(bbase + row1) * HID + jg] = hn1;
        float* orow = out + (size_t)t * (BATCHN * HID);
        orow[(bbase + row0) * HID + jg] = hn0;
        orow[(bbase + row1) * HID + jg] = hn1;

        grp_arrive(sense, cnt, sns);                 // barrier B arrive

        // overlap B: x(t+1) prefetch + z/r x-part for t+1
        az0 = 0; az1 = 0; ar0 = 0; ar1 = 0;
        if (t + 1 < SEQLEN) {
            for (int idx = tid; idx < BT * 32; idx += 256) {
                int row = idx >> 5, c4 = idx & 31;
                *(float4*)(x_s + row * XPAD + c4 * 4) =
                    ((const float4*)X)[(size_t)(bbase + row) * (SEQLEN * INPUTN / 4)
                                       + (size_t)(t + 1) * 32 + c4];
            }
            __syncthreads();
            #pragma unroll 8
            for (int k = 0; k < 32; k++) {
                ulonglong2 xv0 = x0p[k], xv1 = x1p[k];
                ulonglong2 wzv = wz2[64 + k], wrv = wr2[64 + k];
                ffma2(az0, wzv.x, xv0.x); ffma2(az0, wzv.y, xv0.y);
                ffma2(ar0, wrv.x, xv0.x); ffma2(ar0, wrv.y, xv0.y);
                ffma2(az1, wzv.x, xv1.x); ffma2(az1, wzv.y, xv1.y);
                ffma2(ar1, wrv.x, xv1.x); ffma2(ar1, wrv.y, xv1.y);
            }
        }

        grp_wait(sense, sns);                        // barrier B wait

        // refresh h tile for next step
        if (t + 1 < SEQLEN) {
            for (int idx = tid; idx < BT * 64; idx += 256) {
                int row = idx >> 6, c4 = idx & 63;
                *(float4*)(h_s + row * HPAD + c4 * 4) =
                    ((const float4*)g_h)[(bbase + row) * 64 + c4];
            }
            __syncthreads();
        }
    }
}

extern "C" void kernel_launch(void* const* d_in, const int* in_sizes, int n_in,
                              void* d_out, int out_size) {
    const float* X  = (const float*)d_in[0];
    const float* Wz = (const float*)d_in[1];
    const float* bz = (const float*)d_in[2];
    const float* Wr = (const float*)d_in[3];
    const float* br = (const float*)d_in[4];
    const float* Wc = (const float*)d_in[5];
    const float* bc = (const float*)d_in[6];
    float* out = (float*)d_out;

    int smem_floats = 3 * HS * WPAD + 48 + 2 * BT * HPAD + BT * XPAD;
    int smem_bytes  = smem_floats * (int)sizeof(float);

    cudaFuncSetAttribute(gru_persistent,
                         cudaFuncAttributeMaxDynamicSharedMemorySize, smem_bytes);
    gru_persistent<<<NBLK, 256, smem_bytes>>>(X, Wz, bz, Wr, br, Wc, bc, out);
}